// round 2
// baseline (speedup 1.0000x reference)
#include <cuda_runtime.h>
#include <math.h>

// Problem constants (B=1)
#define NATOMS 4096
#define DAD    128
#define DMD    512
#define NPAIR  32768
#define NHEAD  4
#define DHEAD  32
#define DFF    512
#define WIN    16
#define WW     33   // window width

// ---------------- scratch (device globals; no allocation) ----------------
__device__ float g_cond [NATOMS*DAD];
__device__ float g_ada  [NATOMS*512];      // [g1|b1|g2|b2] per row
__device__ float g_qn   [NATOMS*DAD];
__device__ float g_qkvg [NATOMS*512];      // [Q|K|V|G] per row
__device__ float g_att  [NATOMS*DAD];
__device__ float g_attwo[NATOMS*DAD];
__device__ float g_q1   [NATOMS*DAD];
__device__ float g_qn2  [NATOMS*DAD];
__device__ float g_h13  [NATOMS*1024];     // [h1|h3]
__device__ float g_hh   [NATOMS*DFF];
__device__ float g_swi  [NATOMS*DAD];
__device__ float g_gate [NATOMS*256];      // [gate1|gate2]
__device__ float g_biasw[NATOMS*WW*NHEAD];
__device__ int   g_winner[NATOMS*WW];
// packed weights
__device__ float g_wqkvg [DAD*512];
__device__ float g_wadaln[DAD*512];
__device__ float g_badaln[512];
__device__ float g_wgate [DAD*256];
__device__ float g_bgate [256];
__device__ float g_wsw13 [DAD*1024];
__device__ float g_bias2 [DAD];

// ---------------- weight packing ----------------
__global__ void pack_kernel(const float* __restrict__ wq, const float* __restrict__ wk,
                            const float* __restrict__ wv, const float* __restrict__ wg,
                            const float* __restrict__ a1w, const float* __restrict__ a1b,
                            const float* __restrict__ a2w, const float* __restrict__ a2b,
                            const float* __restrict__ g1w, const float* __restrict__ g1b,
                            const float* __restrict__ g2w, const float* __restrict__ g2b,
                            const float* __restrict__ sw1, const float* __restrict__ sw3,
                            const float* __restrict__ cpb, const float* __restrict__ temb)
{
    int i = blockIdx.x * blockDim.x + threadIdx.x;
    int stride = gridDim.x * blockDim.x;
    for (int e = i; e < 128*128; e += stride) {
        int k = e >> 7, n = e & 127;
        g_wqkvg[k*512 +       n] = wq[e];
        g_wqkvg[k*512 + 128 + n] = wk[e];
        g_wqkvg[k*512 + 256 + n] = wv[e];
        g_wqkvg[k*512 + 384 + n] = wg[e];
        g_wgate[k*256 +       n] = g1w[e];
        g_wgate[k*256 + 128 + n] = g2w[e];
    }
    for (int e = i; e < 128*256; e += stride) {
        int k = e >> 8, n = e & 255;
        g_wadaln[k*512 +       n] = a1w[e];
        g_wadaln[k*512 + 256 + n] = a2w[e];
    }
    for (int e = i; e < 128*512; e += stride) {
        int k = e >> 9, n = e & 511;
        g_wsw13[k*1024 +       n] = sw1[e];
        g_wsw13[k*1024 + 512 + n] = sw3[e];
    }
    for (int e = i; e < 256; e += stride) {
        g_badaln[e]       = a1b[e];
        g_badaln[256 + e] = a2b[e];
    }
    for (int e = i; e < 128; e += stride) {
        g_bgate[e]       = g1b[e];
        g_bgate[128 + e] = g2b[e];
        g_bias2[e]       = cpb[e] + temb[e];
    }
}

// ---------------- pair-bias scatter (deterministic last-wins) ----------------
__global__ void scatter_init()
{
    int i = blockIdx.x * blockDim.x + threadIdx.x;
    int stride = gridDim.x * blockDim.x;
    for (int e = i; e < NATOMS*WW; e += stride) g_winner[e] = -1;
    for (int e = i; e < NATOMS*WW*NHEAD; e += stride) g_biasw[e] = 0.0f;
}

__global__ void scatter_pass1(const int* __restrict__ idx)
{
    int p = blockIdx.x * blockDim.x + threadIdx.x;
    if (p >= NPAIR) return;
    int qi = idx[2*p], kj = idx[2*p+1];
    int d = kj - qi;
    if (d >= -WIN && d <= WIN && qi >= 0 && qi < NATOMS && kj >= 0 && kj < NATOMS)
        atomicMax(&g_winner[qi*WW + d + WIN], p);
}

__global__ void scatter_pass2(const int* __restrict__ idx,
                              const float* __restrict__ p_lm,
                              const float* __restrict__ pair_w,
                              const float* __restrict__ pair_b)
{
    int p = blockIdx.x * blockDim.x + threadIdx.x;
    if (p >= NPAIR) return;
    int qi = idx[2*p], kj = idx[2*p+1];
    int d = kj - qi;
    if (!(d >= -WIN && d <= WIN && qi >= 0 && qi < NATOMS && kj >= 0 && kj < NATOMS)) return;
    int slot = qi*WW + d + WIN;
    if (g_winner[slot] != p) return;
    #pragma unroll
    for (int h = 0; h < NHEAD; ++h) {
        float b = pair_b[h];
        #pragma unroll
        for (int k = 0; k < 16; ++k) b += p_lm[p*16 + k] * pair_w[k*NHEAD + h];
        g_biasw[slot*NHEAD + h] = b;
    }
}

// ---------------- fp32 tiled GEMM: C[M,N] = A[M,K] @ B[K,N] (+bias) ----------------
// BM=64, BN=64, BK=16, 256 threads, 4x4 per thread. M%64==0, N%64==0, K%16==0.
__global__ __launch_bounds__(256) void sgemm_k(
    const float* __restrict__ A, const float* __restrict__ Bm,
    const float* __restrict__ bias, float* __restrict__ C,
    int M, int N, int K, const int* __restrict__ rowidx)
{
    __shared__ float As[64][20];   // padded row stride
    __shared__ float Bs[16][64];
    const int tid = threadIdx.x;
    const int tx = tid & 15;       // 0..15 -> col group
    const int ty = tid >> 4;       // 0..15 -> row group
    const int rowBase = blockIdx.y * 64;
    const int colBase = blockIdx.x * 64;
    const int lm = tid >> 2;       // 0..63 A-load row
    const int lk = (tid & 3) * 4;  // 0,4,8,12 A-load k offset
    int arow = rowBase + lm;
    if (rowidx) arow = rowidx[arow];
    const float* Aptr = A + (long)arow * K;

    float acc[4][4] = {};
    for (int k0 = 0; k0 < K; k0 += 16) {
        // A tile: 64 rows x 16 k, float4 per thread
        float4 av = *reinterpret_cast<const float4*>(Aptr + k0 + lk);
        *reinterpret_cast<float4*>(&As[lm][lk]) = av;
        // B tile: 16 k x 64 n
        #pragma unroll
        for (int i = 0; i < 4; ++i) {
            int e = tid + i * 256;
            int kk = e >> 6, n = e & 63;
            Bs[kk][n] = Bm[(long)(k0 + kk) * N + colBase + n];
        }
        __syncthreads();
        #pragma unroll
        for (int kk = 0; kk < 16; ++kk) {
            float4 b4 = *reinterpret_cast<const float4*>(&Bs[kk][tx*4]);
            float bv[4] = {b4.x, b4.y, b4.z, b4.w};
            float avv[4];
            #pragma unroll
            for (int i = 0; i < 4; ++i) avv[i] = As[ty*4 + i][kk];
            #pragma unroll
            for (int i = 0; i < 4; ++i)
                #pragma unroll
                for (int j = 0; j < 4; ++j)
                    acc[i][j] += avv[i] * bv[j];
        }
        __syncthreads();
    }
    #pragma unroll
    for (int i = 0; i < 4; ++i) {
        int r = rowBase + ty*4 + i;
        #pragma unroll
        for (int j = 0; j < 4; ++j) {
            int c = colBase + tx*4 + j;
            float v = acc[i][j];
            if (bias) v += bias[c];
            C[(long)r * N + c] = v;
        }
    }
}

// ---------------- LayerNorm + adaLN modulation ----------------
// ln1: qn = (1+g1) * (LN(q)*ln_g + ln_b) + b1
__global__ void ln1_kernel(const float* __restrict__ q,
                           const float* __restrict__ ln_g, const float* __restrict__ ln_b)
{
    int i = blockIdx.x, d = threadIdx.x;
    __shared__ float red[128];
    float x = q[i*DAD + d];
    red[d] = x; __syncthreads();
    for (int s = 64; s > 0; s >>= 1) { if (d < s) red[d] += red[d+s]; __syncthreads(); }
    float mean = red[0] * (1.0f/128.0f);
    __syncthreads();
    float dev = x - mean;
    red[d] = dev*dev; __syncthreads();
    for (int s = 64; s > 0; s >>= 1) { if (d < s) red[d] += red[d+s]; __syncthreads(); }
    float var = red[0] * (1.0f/128.0f);
    float rstd = rsqrtf(var + 1e-5f);
    float g1 = g_ada[i*512 + d];
    float b1 = g_ada[i*512 + 128 + d];
    float xn = dev * rstd * ln_g[d] + ln_b[d];
    g_qn[i*DAD + d] = (1.0f + g1) * xn + b1;
}

// ln2: qn2 = (1+g2) * LN(q1) + b2   (no affine)
__global__ void ln2_kernel()
{
    int i = blockIdx.x, d = threadIdx.x;
    __shared__ float red[128];
    float x = g_q1[i*DAD + d];
    red[d] = x; __syncthreads();
    for (int s = 64; s > 0; s >>= 1) { if (d < s) red[d] += red[d+s]; __syncthreads(); }
    float mean = red[0] * (1.0f/128.0f);
    __syncthreads();
    float dev = x - mean;
    red[d] = dev*dev; __syncthreads();
    for (int s = 64; s > 0; s >>= 1) { if (d < s) red[d] += red[d+s]; __syncthreads(); }
    float var = red[0] * (1.0f/128.0f);
    float rstd = rsqrtf(var + 1e-5f);
    float g2 = g_ada[i*512 + 256 + d];
    float b2 = g_ada[i*512 + 384 + d];
    g_qn2[i*DAD + d] = (1.0f + g2) * (dev * rstd) + b2;
}

// ---------------- windowed attention: one warp per (atom, head) ----------------
__device__ __forceinline__ float warp_sum(float v)
{
    v += __shfl_xor_sync(0xffffffffu, v, 16);
    v += __shfl_xor_sync(0xffffffffu, v, 8);
    v += __shfl_xor_sync(0xffffffffu, v, 4);
    v += __shfl_xor_sync(0xffffffffu, v, 2);
    v += __shfl_xor_sync(0xffffffffu, v, 1);
    return v;
}

__global__ __launch_bounds__(256) void attn_kernel()
{
    const int lane = threadIdx.x & 31;
    const int gw = blockIdx.x * 8 + (threadIdx.x >> 5);
    const int i = gw >> 2;
    const int h = gw & 3;
    const float scale = 0.17677669529663687f;  // 1/sqrt(32)

    float qv = g_qkvg[i*512 + h*DHEAD + lane];
    float s[WW];
    float mx = -1e30f;
    #pragma unroll
    for (int jj = 0; jj < WW; ++jj) {
        int j = i - WIN + jj;
        float sc = -1e30f;
        if (j >= 0 && j < NATOMS) {
            float kv = g_qkvg[j*512 + 128 + h*DHEAD + lane];
            float dp = warp_sum(qv * kv);
            sc = dp * scale + g_biasw[(i*WW + jj)*NHEAD + h];
        }
        s[jj] = sc;
        mx = fmaxf(mx, sc);
    }
    float sum = 0.0f;
    #pragma unroll
    for (int jj = 0; jj < WW; ++jj) {
        float e = __expf(s[jj] - mx);
        s[jj] = e;
        sum += e;
    }
    float inv = 1.0f / sum;
    float out = 0.0f;
    #pragma unroll
    for (int jj = 0; jj < WW; ++jj) {
        int j = i - WIN + jj;
        if (j >= 0 && j < NATOMS)
            out += s[jj] * inv * g_qkvg[j*512 + 256 + h*DHEAD + lane];
    }
    g_att[i*DAD + h*DHEAD + lane] = out;
}

// ---------------- elementwise fusions ----------------
__device__ __forceinline__ float sigm(float x) { return 1.0f / (1.0f + __expf(-x)); }

// q1 = (q + sigmoid(G) * attwo) * (1 + sigmoid(gate1))
__global__ void q1_kernel(const float* __restrict__ q)
{
    int e = blockIdx.x * blockDim.x + threadIdx.x;
    if (e >= NATOMS*DAD) return;
    int i = e >> 7, d = e & 127;
    float G = g_qkvg[i*512 + 384 + d];
    float v = q[e] + sigm(G) * g_attwo[e];
    v *= (1.0f + sigm(g_gate[i*256 + d]));
    g_q1[e] = v;
}

// hh = silu(h1) * h3
__global__ void hh_kernel()
{
    int e = blockIdx.x * blockDim.x + threadIdx.x;
    if (e >= NATOMS*DFF) return;
    int i = e >> 9, c = e & 511;
    float h1 = g_h13[i*1024 + c];
    float h3 = g_h13[i*1024 + 512 + c];
    g_hh[e] = h1 * sigm(h1) * h3;
}

// out = q1 + sigmoid(gate2) * swi
__global__ void final_kernel(float* __restrict__ out)
{
    int e = blockIdx.x * blockDim.x + threadIdx.x;
    if (e >= NATOMS*DAD) return;
    int i = e >> 7, d = e & 127;
    out[e] = g_q1[e] + sigm(g_gate[i*256 + 128 + d]) * g_swi[e];
}

// ---------------- launch ----------------
extern "C" void kernel_launch(void* const* d_in, const int* in_sizes, int n_in,
                              void* d_out, int out_size)
{
    const float* q        = (const float*)d_in[0];
    const float* c_atom   = (const float*)d_in[1];
    const float* h_cond   = (const float*)d_in[2];
    const float* p_lm     = (const float*)d_in[3];
    const float* t_emb    = (const float*)d_in[4];
    const float* cpw      = (const float*)d_in[5];
    const float* cpb      = (const float*)d_in[6];
    const float* a1w      = (const float*)d_in[7];
    const float* a1b      = (const float*)d_in[8];
    const float* a2w      = (const float*)d_in[9];
    const float* a2b      = (const float*)d_in[10];
    const float* ln_g     = (const float*)d_in[11];
    const float* ln_b     = (const float*)d_in[12];
    const float* wq       = (const float*)d_in[13];
    const float* wk       = (const float*)d_in[14];
    const float* wv       = (const float*)d_in[15];
    const float* wg       = (const float*)d_in[16];
    const float* wo       = (const float*)d_in[17];
    const float* pair_w   = (const float*)d_in[18];
    const float* pair_b   = (const float*)d_in[19];
    const float* g1w      = (const float*)d_in[20];
    const float* g1b      = (const float*)d_in[21];
    const float* g2w      = (const float*)d_in[22];
    const float* g2b      = (const float*)d_in[23];
    const float* sw1      = (const float*)d_in[24];
    const float* sw3      = (const float*)d_in[25];
    const float* sw2      = (const float*)d_in[26];
    const int*   p_lm_idx = (const int*)d_in[27];
    const int*   token_idx= (const int*)d_in[28];
    float* out = (float*)d_out;

    // resolve device-global pointers via symbols is not needed; kernels reference directly.
    pack_kernel<<<128, 256>>>(wq, wk, wv, wg, a1w, a1b, a2w, a2b,
                              g1w, g1b, g2w, g2b, sw1, sw3, cpb, t_emb);
    scatter_init<<<528, 256>>>();
    scatter_pass1<<<NPAIR/256, 256>>>(p_lm_idx);
    scatter_pass2<<<NPAIR/256, 256>>>(p_lm_idx, p_lm, pair_w, pair_b);

    float* d_cond;  cudaGetSymbolAddress((void**)&d_cond,  g_cond);
    float* d_ada;   cudaGetSymbolAddress((void**)&d_ada,   g_ada);
    float* d_qn;    cudaGetSymbolAddress((void**)&d_qn,    g_qn);
    float* d_qkvg;  cudaGetSymbolAddress((void**)&d_qkvg,  g_qkvg);
    float* d_att;   cudaGetSymbolAddress((void**)&d_att,   g_att);
    float* d_attwo; cudaGetSymbolAddress((void**)&d_attwo, g_attwo);
    float* d_qn2;   cudaGetSymbolAddress((void**)&d_qn2,   g_qn2);
    float* d_h13;   cudaGetSymbolAddress((void**)&d_h13,   g_h13);
    float* d_hh;    cudaGetSymbolAddress((void**)&d_hh,    g_hh);
    float* d_swi;   cudaGetSymbolAddress((void**)&d_swi,   g_swi);
    float* d_gate;  cudaGetSymbolAddress((void**)&d_gate,  g_gate);
    float* d_wqkvg; cudaGetSymbolAddress((void**)&d_wqkvg, g_wqkvg);
    float* d_wadaln;cudaGetSymbolAddress((void**)&d_wadaln,g_wadaln);
    float* d_badaln;cudaGetSymbolAddress((void**)&d_badaln,g_badaln);
    float* d_wgate; cudaGetSymbolAddress((void**)&d_wgate, g_wgate);
    float* d_bgate; cudaGetSymbolAddress((void**)&d_bgate, g_bgate);
    float* d_wsw13; cudaGetSymbolAddress((void**)&d_wsw13, g_wsw13);
    float* d_bias2; cudaGetSymbolAddress((void**)&d_bias2, g_bias2);

    // cond = t_emb + h_cond[token_idx] @ cond_proj_w + cond_proj_b   (4096x512x128)
    sgemm_k<<<dim3(128/64, NATOMS/64), 256>>>(h_cond, cpw, d_bias2, d_cond,
                                              NATOMS, 128, 512, token_idx);
    // adaLN 1+2 fused: (4096x128x512)
    sgemm_k<<<dim3(512/64, NATOMS/64), 256>>>(d_cond, d_wadaln, d_badaln, d_ada,
                                              NATOMS, 512, 128, nullptr);
    // gates 1+2 fused from c_atom: (4096x128x256)
    sgemm_k<<<dim3(256/64, NATOMS/64), 256>>>(c_atom, d_wgate, d_bgate, d_gate,
                                              NATOMS, 256, 128, nullptr);
    // qn = adaLN-modulated LayerNorm(q)
    ln1_kernel<<<NATOMS, 128>>>(q, ln_g, ln_b);
    // QKVG fused: (4096x128x512)
    sgemm_k<<<dim3(512/64, NATOMS/64), 256>>>(d_qn, d_wqkvg, nullptr, d_qkvg,
                                              NATOMS, 512, 128, nullptr);
    // windowed attention
    attn_kernel<<<NATOMS*NHEAD/8, 256>>>();
    // att @ wo: (4096x128x128)
    sgemm_k<<<dim3(128/64, NATOMS/64), 256>>>(d_att, wo, nullptr, d_attwo,
                                              NATOMS, 128, 128, nullptr);
    // q1 with output gate + residual gate1
    q1_kernel<<<(NATOMS*DAD + 255)/256, 256>>>(q);
    // second LN + adaLN2
    ln2_kernel<<<NATOMS, 128>>>();
    // swiglu up: (4096x1024x128)
    sgemm_k<<<dim3(1024/64, NATOMS/64), 256>>>(d_qn2, d_wsw13, nullptr, d_h13,
                                               NATOMS, 1024, 128, nullptr);
    hh_kernel<<<(NATOMS*DFF + 255)/256, 256>>>();
    // swiglu down: (4096x128x512)
    sgemm_k<<<dim3(128/64, NATOMS/64), 256>>>(d_hh, sw2, nullptr, d_swi,
                                              NATOMS, 128, 512, nullptr);
    final_kernel<<<(NATOMS*DAD + 255)/256, 256>>>(out);
}

// round 3
// speedup vs baseline: 1.3311x; 1.3311x over previous
#include <cuda_runtime.h>
#include <math.h>
#include <stdint.h>

// Problem constants (B=1)
#define NATOMS 4096
#define DAD    128
#define DMD    512
#define NPAIR  32768
#define NHEAD  4
#define DHEAD  32
#define DFF    512
#define WIN    16
#define WW     33   // window width

// ---------------- scratch (device globals; no allocation) ----------------
__device__ float g_cond [NATOMS*DAD];
__device__ float g_ada  [NATOMS*512];      // [g1|b1|g2|b2] per row
__device__ float g_qn   [NATOMS*DAD];
__device__ float g_qkvg [NATOMS*512];      // [Q|K|V|G] per row
__device__ float g_att  [NATOMS*DAD];
__device__ float g_attwo[NATOMS*DAD];
__device__ float g_q1   [NATOMS*DAD];
__device__ float g_qn2  [NATOMS*DAD];
__device__ float g_h13  [NATOMS*1024];     // [h1|h3]
__device__ float g_hh   [NATOMS*DFF];
__device__ float g_swi  [NATOMS*DAD];
__device__ float g_gate [NATOMS*256];      // [gate1|gate2]
__device__ float g_biasw[NATOMS*WW*NHEAD];
__device__ int   g_winner[NATOMS*WW];
// packed weights
__device__ float g_wqkvg [DAD*512];
__device__ float g_wadaln[DAD*512];
__device__ float g_badaln[512];
__device__ float g_wgate [DAD*256];
__device__ float g_bgate [256];
__device__ float g_wsw13 [DAD*1024];
__device__ float g_bias2 [DAD];

// ---------------- weight packing ----------------
__global__ void pack_kernel(const float* __restrict__ wq, const float* __restrict__ wk,
                            const float* __restrict__ wv, const float* __restrict__ wg,
                            const float* __restrict__ a1w, const float* __restrict__ a1b,
                            const float* __restrict__ a2w, const float* __restrict__ a2b,
                            const float* __restrict__ g1w, const float* __restrict__ g1b,
                            const float* __restrict__ g2w, const float* __restrict__ g2b,
                            const float* __restrict__ sw1, const float* __restrict__ sw3,
                            const float* __restrict__ cpb, const float* __restrict__ temb)
{
    int i = blockIdx.x * blockDim.x + threadIdx.x;
    int stride = gridDim.x * blockDim.x;
    for (int e = i; e < 128*128; e += stride) {
        int k = e >> 7, n = e & 127;
        g_wqkvg[k*512 +       n] = wq[e];
        g_wqkvg[k*512 + 128 + n] = wk[e];
        g_wqkvg[k*512 + 256 + n] = wv[e];
        g_wqkvg[k*512 + 384 + n] = wg[e];
        g_wgate[k*256 +       n] = g1w[e];
        g_wgate[k*256 + 128 + n] = g2w[e];
    }
    for (int e = i; e < 128*256; e += stride) {
        int k = e >> 8, n = e & 255;
        g_wadaln[k*512 +       n] = a1w[e];
        g_wadaln[k*512 + 256 + n] = a2w[e];
    }
    for (int e = i; e < 128*512; e += stride) {
        int k = e >> 9, n = e & 511;
        g_wsw13[k*1024 +       n] = sw1[e];
        g_wsw13[k*1024 + 512 + n] = sw3[e];
    }
    for (int e = i; e < 256; e += stride) {
        g_badaln[e]       = a1b[e];
        g_badaln[256 + e] = a2b[e];
    }
    for (int e = i; e < 128; e += stride) {
        g_bgate[e]       = g1b[e];
        g_bgate[128 + e] = g2b[e];
        g_bias2[e]       = cpb[e] + temb[e];
    }
}

// ---------------- pair-bias scatter (deterministic last-wins) ----------------
__global__ void scatter_init()
{
    int i = blockIdx.x * blockDim.x + threadIdx.x;
    int stride = gridDim.x * blockDim.x;
    for (int e = i; e < NATOMS*WW; e += stride) g_winner[e] = -1;
    for (int e = i; e < NATOMS*WW*NHEAD; e += stride) g_biasw[e] = 0.0f;
}

__global__ void scatter_pass1(const int* __restrict__ idx)
{
    int p = blockIdx.x * blockDim.x + threadIdx.x;
    if (p >= NPAIR) return;
    int qi = idx[2*p], kj = idx[2*p+1];
    int d = kj - qi;
    if (d >= -WIN && d <= WIN && qi >= 0 && qi < NATOMS && kj >= 0 && kj < NATOMS)
        atomicMax(&g_winner[qi*WW + d + WIN], p);
}

__global__ void scatter_pass2(const int* __restrict__ idx,
                              const float* __restrict__ p_lm,
                              const float* __restrict__ pair_w,
                              const float* __restrict__ pair_b)
{
    int p = blockIdx.x * blockDim.x + threadIdx.x;
    if (p >= NPAIR) return;
    int qi = idx[2*p], kj = idx[2*p+1];
    int d = kj - qi;
    if (!(d >= -WIN && d <= WIN && qi >= 0 && qi < NATOMS && kj >= 0 && kj < NATOMS)) return;
    int slot = qi*WW + d + WIN;
    if (g_winner[slot] != p) return;
    #pragma unroll
    for (int h = 0; h < NHEAD; ++h) {
        float b = pair_b[h];
        #pragma unroll
        for (int k = 0; k < 16; ++k) b += p_lm[p*16 + k] * pair_w[k*NHEAD + h];
        g_biasw[slot*NHEAD + h] = b;
    }
}

// ---------------- TF32 tensor-core GEMM ----------------
// C[M,N] = A[M,K] @ B[K,N] (+bias), A/B row-major fp32 in gmem, tf32 mma.
// Tile: BM=64, BN=64, BK=16. 128 threads = 4 warps (warpM=wid&1? no: 2x2),
// warp tile 32x32 built from m16n8k8 atoms (2 along M, 4 along N).
__device__ __forceinline__ uint32_t f2tf32(float x)
{
    uint32_t r;
    asm("cvt.rna.tf32.f32 %0, %1;" : "=r"(r) : "f"(x));
    return r;
}

__device__ __forceinline__ void mma_tf32(float* c, const uint32_t* a, const uint32_t* b)
{
    asm volatile(
        "mma.sync.aligned.m16n8k8.row.col.f32.tf32.tf32.f32 "
        "{%0,%1,%2,%3}, {%4,%5,%6,%7}, {%8,%9}, {%0,%1,%2,%3};\n"
        : "+f"(c[0]), "+f"(c[1]), "+f"(c[2]), "+f"(c[3])
        : "r"(a[0]), "r"(a[1]), "r"(a[2]), "r"(a[3]), "r"(b[0]), "r"(b[1]));
}

#define AS_STRIDE 20   // As[row][k], 64 rows x 16 k, pad to 20 -> conflict-free frag loads
#define BS_STRIDE 68   // Bs[k][n], 16 k x 64 n, pad to 68 -> conflict-free frag loads

__global__ __launch_bounds__(128) void tgemm_k(
    const float* __restrict__ A, const float* __restrict__ Bm,
    const float* __restrict__ bias, float* __restrict__ C,
    int M, int N, int K, const int* __restrict__ rowidx)
{
    __shared__ uint32_t As[64 * AS_STRIDE];
    __shared__ uint32_t Bs[16 * BS_STRIDE];

    const int tid  = threadIdx.x;
    const int wid  = tid >> 5;
    const int lane = tid & 31;
    const int gid  = lane >> 2;   // 0..7
    const int tig  = lane & 3;    // 0..3
    const int warpM = wid & 1;    // 2 warps along M
    const int warpN = wid >> 1;   // 2 warps along N
    const int rowBase = blockIdx.y * 64;
    const int colBase = blockIdx.x * 64;

    // global-load coordinates
    const int a_row  = tid >> 2;           // 0..31 (2 iters cover 64 rows? no: see below)
    const int a_koff = (tid & 3) * 4;
    const int b_krow = tid >> 4;           // 0..7 (2 iters cover 16)
    const int b_noff = (tid & 15) * 4;

    // resolve the two A rows this thread loads (A tile = 64x16 = 256 float4; 128 thr -> 2 each)
    long arow0, arow1;
    {
        int r0 = rowBase + a_row;        // ids 0..127 -> rows 0..31
        int r1 = rowBase + a_row + 32;   // ids 128..255 -> rows 32..63
        arow0 = rowidx ? rowidx[r0] : r0;
        arow1 = rowidx ? rowidx[r1] : r1;
    }

    float acc[2][4][4];
    #pragma unroll
    for (int mi = 0; mi < 2; ++mi)
        #pragma unroll
        for (int ni = 0; ni < 4; ++ni)
            #pragma unroll
            for (int t = 0; t < 4; ++t) acc[mi][ni][t] = 0.0f;

    for (int k0 = 0; k0 < K; k0 += 16) {
        // A tile -> smem (tf32-converted)
        {
            float4 v0 = *reinterpret_cast<const float4*>(A + arow0 * K + k0 + a_koff);
            float4 v1 = *reinterpret_cast<const float4*>(A + arow1 * K + k0 + a_koff);
            uint32_t* p0 = &As[a_row * AS_STRIDE + a_koff];
            uint32_t* p1 = &As[(a_row + 32) * AS_STRIDE + a_koff];
            p0[0] = f2tf32(v0.x); p0[1] = f2tf32(v0.y); p0[2] = f2tf32(v0.z); p0[3] = f2tf32(v0.w);
            p1[0] = f2tf32(v1.x); p1[1] = f2tf32(v1.y); p1[2] = f2tf32(v1.z); p1[3] = f2tf32(v1.w);
        }
        // B tile -> smem (tf32-converted); 16x64 = 256 float4; 2 per thread
        {
            #pragma unroll
            for (int i = 0; i < 2; ++i) {
                int kk = b_krow + i * 8;
                float4 v = *reinterpret_cast<const float4*>(Bm + (long)(k0 + kk) * N + colBase + b_noff);
                uint32_t* p = &Bs[kk * BS_STRIDE + b_noff];
                p[0] = f2tf32(v.x); p[1] = f2tf32(v.y); p[2] = f2tf32(v.z); p[3] = f2tf32(v.w);
            }
        }
        __syncthreads();

        #pragma unroll
        for (int ks = 0; ks < 2; ++ks) {
            const int kk = ks * 8;
            uint32_t afrag[2][4];
            uint32_t bfrag[4][2];
            #pragma unroll
            for (int mi = 0; mi < 2; ++mi) {
                int r0 = warpM * 32 + mi * 16 + gid;
                afrag[mi][0] = As[r0 * AS_STRIDE + kk + tig];
                afrag[mi][1] = As[(r0 + 8) * AS_STRIDE + kk + tig];
                afrag[mi][2] = As[r0 * AS_STRIDE + kk + tig + 4];
                afrag[mi][3] = As[(r0 + 8) * AS_STRIDE + kk + tig + 4];
            }
            #pragma unroll
            for (int ni = 0; ni < 4; ++ni) {
                int n0 = warpN * 32 + ni * 8 + gid;
                bfrag[ni][0] = Bs[(kk + tig) * BS_STRIDE + n0];
                bfrag[ni][1] = Bs[(kk + tig + 4) * BS_STRIDE + n0];
            }
            #pragma unroll
            for (int mi = 0; mi < 2; ++mi)
                #pragma unroll
                for (int ni = 0; ni < 4; ++ni)
                    mma_tf32(acc[mi][ni], afrag[mi], bfrag[ni]);
        }
        __syncthreads();
    }

    // epilogue
    #pragma unroll
    for (int mi = 0; mi < 2; ++mi) {
        int r0 = rowBase + warpM * 32 + mi * 16 + gid;
        #pragma unroll
        for (int ni = 0; ni < 4; ++ni) {
            int c0 = colBase + warpN * 32 + ni * 8 + 2 * tig;
            float b0 = bias ? bias[c0]     : 0.0f;
            float b1 = bias ? bias[c0 + 1] : 0.0f;
            float2 v0 = make_float2(acc[mi][ni][0] + b0, acc[mi][ni][1] + b1);
            float2 v1 = make_float2(acc[mi][ni][2] + b0, acc[mi][ni][3] + b1);
            *reinterpret_cast<float2*>(C + (long)r0 * N + c0)       = v0;
            *reinterpret_cast<float2*>(C + (long)(r0 + 8) * N + c0) = v1;
        }
    }
}

// ---------------- LayerNorm + adaLN modulation ----------------
__global__ void ln1_kernel(const float* __restrict__ q,
                           const float* __restrict__ ln_g, const float* __restrict__ ln_b)
{
    int i = blockIdx.x, d = threadIdx.x;
    __shared__ float red[128];
    float x = q[i*DAD + d];
    red[d] = x; __syncthreads();
    for (int s = 64; s > 0; s >>= 1) { if (d < s) red[d] += red[d+s]; __syncthreads(); }
    float mean = red[0] * (1.0f/128.0f);
    __syncthreads();
    float dev = x - mean;
    red[d] = dev*dev; __syncthreads();
    for (int s = 64; s > 0; s >>= 1) { if (d < s) red[d] += red[d+s]; __syncthreads(); }
    float var = red[0] * (1.0f/128.0f);
    float rstd = rsqrtf(var + 1e-5f);
    float g1 = g_ada[i*512 + d];
    float b1 = g_ada[i*512 + 128 + d];
    float xn = dev * rstd * ln_g[d] + ln_b[d];
    g_qn[i*DAD + d] = (1.0f + g1) * xn + b1;
}

__global__ void ln2_kernel()
{
    int i = blockIdx.x, d = threadIdx.x;
    __shared__ float red[128];
    float x = g_q1[i*DAD + d];
    red[d] = x; __syncthreads();
    for (int s = 64; s > 0; s >>= 1) { if (d < s) red[d] += red[d+s]; __syncthreads(); }
    float mean = red[0] * (1.0f/128.0f);
    __syncthreads();
    float dev = x - mean;
    red[d] = dev*dev; __syncthreads();
    for (int s = 64; s > 0; s >>= 1) { if (d < s) red[d] += red[d+s]; __syncthreads(); }
    float var = red[0] * (1.0f/128.0f);
    float rstd = rsqrtf(var + 1e-5f);
    float g2 = g_ada[i*512 + 256 + d];
    float b2 = g_ada[i*512 + 384 + d];
    g_qn2[i*DAD + d] = (1.0f + g2) * (dev * rstd) + b2;
}

// ---------------- windowed attention: one warp per (atom, head) ----------------
__device__ __forceinline__ float warp_sum(float v)
{
    v += __shfl_xor_sync(0xffffffffu, v, 16);
    v += __shfl_xor_sync(0xffffffffu, v, 8);
    v += __shfl_xor_sync(0xffffffffu, v, 4);
    v += __shfl_xor_sync(0xffffffffu, v, 2);
    v += __shfl_xor_sync(0xffffffffu, v, 1);
    return v;
}

__global__ __launch_bounds__(256) void attn_kernel()
{
    const int lane = threadIdx.x & 31;
    const int gw = blockIdx.x * 8 + (threadIdx.x >> 5);
    const int i = gw >> 2;
    const int h = gw & 3;
    const float scale = 0.17677669529663687f;  // 1/sqrt(32)

    float qv = g_qkvg[i*512 + h*DHEAD + lane];
    float s[WW];
    float mx = -1e30f;
    #pragma unroll
    for (int jj = 0; jj < WW; ++jj) {
        int j = i - WIN + jj;
        float sc = -1e30f;
        if (j >= 0 && j < NATOMS) {
            float kv = g_qkvg[j*512 + 128 + h*DHEAD + lane];
            float dp = warp_sum(qv * kv);
            sc = dp * scale + g_biasw[(i*WW + jj)*NHEAD + h];
        }
        s[jj] = sc;
        mx = fmaxf(mx, sc);
    }
    float sum = 0.0f;
    #pragma unroll
    for (int jj = 0; jj < WW; ++jj) {
        float e = __expf(s[jj] - mx);
        s[jj] = e;
        sum += e;
    }
    float inv = 1.0f / sum;
    float out = 0.0f;
    #pragma unroll
    for (int jj = 0; jj < WW; ++jj) {
        int j = i - WIN + jj;
        if (j >= 0 && j < NATOMS)
            out += s[jj] * inv * g_qkvg[j*512 + 256 + h*DHEAD + lane];
    }
    g_att[i*DAD + h*DHEAD + lane] = out;
}

// ---------------- elementwise fusions ----------------
__device__ __forceinline__ float sigm(float x) { return 1.0f / (1.0f + __expf(-x)); }

__global__ void q1_kernel(const float* __restrict__ q)
{
    int e = blockIdx.x * blockDim.x + threadIdx.x;
    if (e >= NATOMS*DAD) return;
    int i = e >> 7, d = e & 127;
    float G = g_qkvg[i*512 + 384 + d];
    float v = q[e] + sigm(G) * g_attwo[e];
    v *= (1.0f + sigm(g_gate[i*256 + d]));
    g_q1[e] = v;
}

__global__ void hh_kernel()
{
    int e = blockIdx.x * blockDim.x + threadIdx.x;
    if (e >= NATOMS*DFF) return;
    int i = e >> 9, c = e & 511;
    float h1 = g_h13[i*1024 + c];
    float h3 = g_h13[i*1024 + 512 + c];
    g_hh[e] = h1 * sigm(h1) * h3;
}

__global__ void final_kernel(float* __restrict__ out)
{
    int e = blockIdx.x * blockDim.x + threadIdx.x;
    if (e >= NATOMS*DAD) return;
    int i = e >> 7, d = e & 127;
    out[e] = g_q1[e] + sigm(g_gate[i*256 + 128 + d]) * g_swi[e];
}

// ---------------- launch ----------------
extern "C" void kernel_launch(void* const* d_in, const int* in_sizes, int n_in,
                              void* d_out, int out_size)
{
    const float* q        = (const float*)d_in[0];
    const float* c_atom   = (const float*)d_in[1];
    const float* h_cond   = (const float*)d_in[2];
    const float* p_lm     = (const float*)d_in[3];
    const float* t_emb    = (const float*)d_in[4];
    const float* cpw      = (const float*)d_in[5];
    const float* cpb      = (const float*)d_in[6];
    const float* a1w      = (const float*)d_in[7];
    const float* a1b      = (const float*)d_in[8];
    const float* a2w      = (const float*)d_in[9];
    const float* a2b      = (const float*)d_in[10];
    const float* ln_g     = (const float*)d_in[11];
    const float* ln_b     = (const float*)d_in[12];
    const float* wq       = (const float*)d_in[13];
    const float* wk       = (const float*)d_in[14];
    const float* wv       = (const float*)d_in[15];
    const float* wg       = (const float*)d_in[16];
    const float* wo       = (const float*)d_in[17];
    const float* pair_w   = (const float*)d_in[18];
    const float* pair_b   = (const float*)d_in[19];
    const float* g1w      = (const float*)d_in[20];
    const float* g1b      = (const float*)d_in[21];
    const float* g2w      = (const float*)d_in[22];
    const float* g2b      = (const float*)d_in[23];
    const float* sw1      = (const float*)d_in[24];
    const float* sw3      = (const float*)d_in[25];
    const float* sw2      = (const float*)d_in[26];
    const int*   p_lm_idx = (const int*)d_in[27];
    const int*   token_idx= (const int*)d_in[28];
    float* out = (float*)d_out;

    pack_kernel<<<128, 256>>>(wq, wk, wv, wg, a1w, a1b, a2w, a2b,
                              g1w, g1b, g2w, g2b, sw1, sw3, cpb, t_emb);
    scatter_init<<<528, 256>>>();
    scatter_pass1<<<NPAIR/256, 256>>>(p_lm_idx);
    scatter_pass2<<<NPAIR/256, 256>>>(p_lm_idx, p_lm, pair_w, pair_b);

    float* d_cond;  cudaGetSymbolAddress((void**)&d_cond,  g_cond);
    float* d_ada;   cudaGetSymbolAddress((void**)&d_ada,   g_ada);
    float* d_qn;    cudaGetSymbolAddress((void**)&d_qn,    g_qn);
    float* d_qkvg;  cudaGetSymbolAddress((void**)&d_qkvg,  g_qkvg);
    float* d_att;   cudaGetSymbolAddress((void**)&d_att,   g_att);
    float* d_attwo; cudaGetSymbolAddress((void**)&d_attwo, g_attwo);
    float* d_qn2;   cudaGetSymbolAddress((void**)&d_qn2,   g_qn2);
    float* d_h13;   cudaGetSymbolAddress((void**)&d_h13,   g_h13);
    float* d_hh;    cudaGetSymbolAddress((void**)&d_hh,    g_hh);
    float* d_swi;   cudaGetSymbolAddress((void**)&d_swi,   g_swi);
    float* d_gate;  cudaGetSymbolAddress((void**)&d_gate,  g_gate);
    float* d_wqkvg; cudaGetSymbolAddress((void**)&d_wqkvg, g_wqkvg);
    float* d_wadaln;cudaGetSymbolAddress((void**)&d_wadaln,g_wadaln);
    float* d_badaln;cudaGetSymbolAddress((void**)&d_badaln,g_badaln);
    float* d_wgate; cudaGetSymbolAddress((void**)&d_wgate, g_wgate);
    float* d_bgate; cudaGetSymbolAddress((void**)&d_bgate, g_bgate);
    float* d_wsw13; cudaGetSymbolAddress((void**)&d_wsw13, g_wsw13);
    float* d_bias2; cudaGetSymbolAddress((void**)&d_bias2, g_bias2);

    // cond = t_emb + h_cond[token_idx] @ cond_proj_w + cond_proj_b   (4096x128x512)
    tgemm_k<<<dim3(128/64, NATOMS/64), 128>>>(h_cond, cpw, d_bias2, d_cond,
                                              NATOMS, 128, 512, token_idx);
    // adaLN 1+2 fused: (4096x512x128)
    tgemm_k<<<dim3(512/64, NATOMS/64), 128>>>(d_cond, d_wadaln, d_badaln, d_ada,
                                              NATOMS, 512, 128, nullptr);
    // gates 1+2 fused from c_atom: (4096x256x128)
    tgemm_k<<<dim3(256/64, NATOMS/64), 128>>>(c_atom, d_wgate, d_bgate, d_gate,
                                              NATOMS, 256, 128, nullptr);
    // qn = adaLN-modulated LayerNorm(q)
    ln1_kernel<<<NATOMS, 128>>>(q, ln_g, ln_b);
    // QKVG fused: (4096x512x128)
    tgemm_k<<<dim3(512/64, NATOMS/64), 128>>>(d_qn, d_wqkvg, nullptr, d_qkvg,
                                              NATOMS, 512, 128, nullptr);
    // windowed attention
    attn_kernel<<<NATOMS*NHEAD/8, 256>>>();
    // att @ wo: (4096x128x128)
    tgemm_k<<<dim3(128/64, NATOMS/64), 128>>>(d_att, wo, nullptr, d_attwo,
                                              NATOMS, 128, 128, nullptr);
    // q1 with output gate + residual gate1
    q1_kernel<<<(NATOMS*DAD + 255)/256, 256>>>(q);
    // second LN + adaLN2
    ln2_kernel<<<NATOMS, 128>>>();
    // swiglu up: (4096x1024x128)
    tgemm_k<<<dim3(1024/64, NATOMS/64), 128>>>(d_qn2, d_wsw13, nullptr, d_h13,
                                               NATOMS, 1024, 128, nullptr);
    hh_kernel<<<(NATOMS*DFF + 255)/256, 256>>>();
    // swiglu down: (4096x128x512)
    tgemm_k<<<dim3(128/64, NATOMS/64), 128>>>(d_hh, sw2, nullptr, d_swi,
                                              NATOMS, 128, 512, nullptr);
    final_kernel<<<(NATOMS*DAD + 255)/256, 256>>>(out);
}

// round 4
// speedup vs baseline: 1.5619x; 1.1734x over previous
#include <cuda_runtime.h>
#include <math.h>
#include <stdint.h>

// Problem constants (B=1)
#define NATOMS 4096
#define DAD    128
#define NPAIR  32768
#define NHEAD  4
#define DHEAD  32
#define DFF    512
#define WIN    16
#define WW     33   // window width

// ---------------- scratch (device globals; no allocation) ----------------
__device__ float g_cond [NATOMS*DAD];
__device__ float g_ada  [NATOMS*512];      // [g1|b1|g2|b2] per row
__device__ float g_qn   [NATOMS*DAD];
__device__ float g_qkvg [NATOMS*512];      // [Q|K|V|G] per row
__device__ float g_att  [NATOMS*DAD];
__device__ float g_q1   [NATOMS*DAD];
__device__ float g_qn2  [NATOMS*DAD];
__device__ float g_hh   [NATOMS*DFF];
__device__ float g_gate [NATOMS*256];      // [gate1|gate2]
__device__ float g_biasw[NATOMS*WW*NHEAD];
__device__ int   g_winner[NATOMS*WW];
// packed weights
__device__ float g_wqkvg [DAD*512];
__device__ float g_wadaln[DAD*512];
__device__ float g_badaln[512];
__device__ float g_wgate [DAD*256];
__device__ float g_bgate [256];
__device__ float g_wsw13 [DAD*1024];       // interleaved: col 2c = sw1_c, 2c+1 = sw3_c
__device__ float g_bias2 [DAD];

__device__ __forceinline__ float sigm(float x) { return 1.0f / (1.0f + __expf(-x)); }

__device__ __forceinline__ uint32_t f2tf32(float x)
{
    uint32_t r;
    asm("cvt.rna.tf32.f32 %0, %1;" : "=r"(r) : "f"(x));
    return r;
}

__device__ __forceinline__ void mma_tf32(float* c, const uint32_t* a, const uint32_t* b)
{
    asm volatile(
        "mma.sync.aligned.m16n8k8.row.col.f32.tf32.tf32.f32 "
        "{%0,%1,%2,%3}, {%4,%5,%6,%7}, {%8,%9}, {%0,%1,%2,%3};\n"
        : "+f"(c[0]), "+f"(c[1]), "+f"(c[2]), "+f"(c[3])
        : "r"(a[0]), "r"(a[1]), "r"(a[2]), "r"(a[3]), "r"(b[0]), "r"(b[1]));
}

// ---------------- weight packing ----------------
__global__ void pack_kernel(const float* __restrict__ wq, const float* __restrict__ wk,
                            const float* __restrict__ wv, const float* __restrict__ wg,
                            const float* __restrict__ a1w, const float* __restrict__ a1b,
                            const float* __restrict__ a2w, const float* __restrict__ a2b,
                            const float* __restrict__ g1w, const float* __restrict__ g1b,
                            const float* __restrict__ g2w, const float* __restrict__ g2b,
                            const float* __restrict__ sw1, const float* __restrict__ sw3,
                            const float* __restrict__ cpb, const float* __restrict__ temb)
{
    int i = blockIdx.x * blockDim.x + threadIdx.x;
    int stride = gridDim.x * blockDim.x;
    for (int e = i; e < 128*128; e += stride) {
        int k = e >> 7, n = e & 127;
        g_wqkvg[k*512 +       n] = wq[e];
        g_wqkvg[k*512 + 128 + n] = wk[e];
        g_wqkvg[k*512 + 256 + n] = wv[e];
        g_wqkvg[k*512 + 384 + n] = wg[e];
        g_wgate[k*256 +       n] = g1w[e];
        g_wgate[k*256 + 128 + n] = g2w[e];
    }
    for (int e = i; e < 128*256; e += stride) {
        int k = e >> 8, n = e & 255;
        g_wadaln[k*512 +       n] = a1w[e];
        g_wadaln[k*512 + 256 + n] = a2w[e];
    }
    for (int e = i; e < 128*512; e += stride) {
        int k = e >> 9, n = e & 511;
        g_wsw13[k*1024 + 2*n    ] = sw1[e];
        g_wsw13[k*1024 + 2*n + 1] = sw3[e];
    }
    for (int e = i; e < 256; e += stride) {
        g_badaln[e]       = a1b[e];
        g_badaln[256 + e] = a2b[e];
    }
    for (int e = i; e < 128; e += stride) {
        g_bgate[e]       = g1b[e];
        g_bgate[128 + e] = g2b[e];
        g_bias2[e]       = cpb[e] + temb[e];
    }
}

// ---------------- pair-bias scatter (deterministic last-wins) ----------------
__global__ void scatter_init()
{
    int i = blockIdx.x * blockDim.x + threadIdx.x;
    int stride = gridDim.x * blockDim.x;
    for (int e = i; e < NATOMS*WW; e += stride) g_winner[e] = -1;
    for (int e = i; e < NATOMS*WW*NHEAD; e += stride) g_biasw[e] = 0.0f;
}

__global__ void scatter_pass1(const int* __restrict__ idx)
{
    int p = blockIdx.x * blockDim.x + threadIdx.x;
    if (p >= NPAIR) return;
    int qi = idx[2*p], kj = idx[2*p+1];
    int d = kj - qi;
    if (d >= -WIN && d <= WIN && qi >= 0 && qi < NATOMS && kj >= 0 && kj < NATOMS)
        atomicMax(&g_winner[qi*WW + d + WIN], p);
}

__global__ void scatter_pass2(const int* __restrict__ idx,
                              const float* __restrict__ p_lm,
                              const float* __restrict__ pair_w,
                              const float* __restrict__ pair_b)
{
    int p = blockIdx.x * blockDim.x + threadIdx.x;
    if (p >= NPAIR) return;
    int qi = idx[2*p], kj = idx[2*p+1];
    int d = kj - qi;
    if (!(d >= -WIN && d <= WIN && qi >= 0 && qi < NATOMS && kj >= 0 && kj < NATOMS)) return;
    int slot = qi*WW + d + WIN;
    if (g_winner[slot] != p) return;
    #pragma unroll
    for (int h = 0; h < NHEAD; ++h) {
        float b = pair_b[h];
        #pragma unroll
        for (int k = 0; k < 16; ++k) b += p_lm[p*16 + k] * pair_w[k*NHEAD + h];
        g_biasw[slot*NHEAD + h] = b;
    }
}

// ---------------- pipelined TF32 tensor-core GEMM ----------------
// C[M,N] = A[M,K] @ B[K,N]; double-buffered smem, one sync per BK=32 k-iter.
// MODE 0: +bias plain store. 1: swiglu (interleaved h1/h3 -> silu(h1)*h3, out N/2).
// 2: q1 fuse: C = (aux0 + sigm(aux1_G)*acc) * (1+sigm(aux2_gate1)).
// 3: final fuse: C = aux0 + sigm(aux2_gate2)*acc.
template<int BM, int BN, int BK, int WM, int WN, int MODE>
__global__ __launch_bounds__(32*WM*WN)
void tgemm(const float* __restrict__ A, const float* __restrict__ Bm,
           const float* __restrict__ bias, float* __restrict__ C,
           int M, int N, int K, const int* __restrict__ rowidx,
           const float* __restrict__ aux0, const float* __restrict__ aux1,
           const float* __restrict__ aux2)
{
    constexpr int THREADS = 32*WM*WN;
    constexpr int WTM = BM/WM, WTN = BN/WN;
    constexpr int AM = WTM/16, AN = WTN/8;
    constexpr int AS = BK + 4;   // stride ≡ 4 (mod 32) -> conflict-free frag loads
    constexpr int BS = BN + 4;
    constexpr int LA = BM*BK/(4*THREADS);
    constexpr int LB = BK*BN/(4*THREADS);
    constexpr int A_TPR = BK/4;              // threads per A row (float4)
    constexpr int A_RSTEP = THREADS/A_TPR;
    constexpr int B_TPR = BN/4;
    constexpr int B_KSTEP = THREADS/B_TPR;

    __shared__ uint32_t As[2][BM*AS];
    __shared__ uint32_t Bs[2][BK*BS];

    const int tid = threadIdx.x;
    const int wid = tid >> 5, lane = tid & 31;
    const int gid = lane >> 2, tig = lane & 3;
    const int warpM = wid % WM, warpN = wid / WM;
    const int rowBase = blockIdx.y * BM, colBase = blockIdx.x * BN;

    const int a_r = tid / A_TPR;
    const int a_k = (tid % A_TPR) * 4;
    const int b_k = tid / B_TPR;
    const int b_n = (tid % B_TPR) * 4;

    long arowg[LA];
    #pragma unroll
    for (int a = 0; a < LA; ++a) {
        int r = rowBase + a_r + a*A_RSTEP;
        arowg[a] = rowidx ? (long)rowidx[r] : (long)r;
    }

    float4 ra[LA], rb[LB];

    auto loadg = [&](int it) {
        int k0 = it * BK;
        #pragma unroll
        for (int a = 0; a < LA; ++a)
            ra[a] = *reinterpret_cast<const float4*>(A + arowg[a]*K + k0 + a_k);
        #pragma unroll
        for (int b = 0; b < LB; ++b)
            rb[b] = *reinterpret_cast<const float4*>(Bm + (long)(k0 + b_k + b*B_KSTEP)*N + colBase + b_n);
    };
    auto stores = [&](int bf) {
        #pragma unroll
        for (int a = 0; a < LA; ++a) {
            uint32_t* p = &As[bf][(a_r + a*A_RSTEP)*AS + a_k];
            p[0]=f2tf32(ra[a].x); p[1]=f2tf32(ra[a].y); p[2]=f2tf32(ra[a].z); p[3]=f2tf32(ra[a].w);
        }
        #pragma unroll
        for (int b = 0; b < LB; ++b) {
            uint32_t* p = &Bs[bf][(b_k + b*B_KSTEP)*BS + b_n];
            p[0]=f2tf32(rb[b].x); p[1]=f2tf32(rb[b].y); p[2]=f2tf32(rb[b].z); p[3]=f2tf32(rb[b].w);
        }
    };

    float acc[AM][AN][4] = {};

    loadg(0); stores(0); __syncthreads();
    const int nIter = K / BK;
    int bf = 0;
    for (int it = 0; it < nIter; ++it) {
        if (it + 1 < nIter) loadg(it + 1);
        #pragma unroll
        for (int ks = 0; ks < BK/8; ++ks) {
            const int kk = ks * 8;
            uint32_t af[AM][4], bfr[AN][2];
            #pragma unroll
            for (int mi = 0; mi < AM; ++mi) {
                int r0 = warpM*WTM + mi*16 + gid;
                af[mi][0] = As[bf][r0*AS + kk + tig];
                af[mi][1] = As[bf][(r0+8)*AS + kk + tig];
                af[mi][2] = As[bf][r0*AS + kk + tig + 4];
                af[mi][3] = As[bf][(r0+8)*AS + kk + tig + 4];
            }
            #pragma unroll
            for (int ni = 0; ni < AN; ++ni) {
                int n0 = warpN*WTN + ni*8 + gid;
                bfr[ni][0] = Bs[bf][(kk + tig)*BS + n0];
                bfr[ni][1] = Bs[bf][(kk + tig + 4)*BS + n0];
            }
            #pragma unroll
            for (int mi = 0; mi < AM; ++mi)
                #pragma unroll
                for (int ni = 0; ni < AN; ++ni)
                    mma_tf32(acc[mi][ni], af[mi], bfr[ni]);
        }
        if (it + 1 < nIter) stores(bf ^ 1);
        __syncthreads();
        bf ^= 1;
    }

    // ---------------- epilogue ----------------
    #pragma unroll
    for (int mi = 0; mi < AM; ++mi) {
        #pragma unroll
        for (int ni = 0; ni < AN; ++ni) {
            int c0 = colBase + warpN*WTN + ni*8 + 2*tig;
            #pragma unroll
            for (int rh = 0; rh < 2; ++rh) {
                int r = rowBase + warpM*WTM + mi*16 + gid + rh*8;
                float v0 = acc[mi][ni][rh*2 + 0];
                float v1 = acc[mi][ni][rh*2 + 1];
                if (MODE == 0) {
                    if (bias) { v0 += bias[c0]; v1 += bias[c0+1]; }
                    *reinterpret_cast<float2*>(C + (long)r*N + c0) = make_float2(v0, v1);
                } else if (MODE == 1) {
                    // interleaved (h1, h3) -> silu(h1)*h3, out width N/2
                    C[(long)r*(N >> 1) + (c0 >> 1)] = v0 * sigm(v0) * v1;
                } else if (MODE == 2) {
                    float q0 = aux0[r*128 + c0],   q1v = aux0[r*128 + c0 + 1];
                    float G0 = aux1[r*512 + 384 + c0], G1 = aux1[r*512 + 384 + c0 + 1];
                    float t0 = aux2[r*256 + c0],   t1 = aux2[r*256 + c0 + 1];
                    float o0 = (q0 + sigm(G0)*v0) * (1.0f + sigm(t0));
                    float o1 = (q1v + sigm(G1)*v1) * (1.0f + sigm(t1));
                    *reinterpret_cast<float2*>(C + (long)r*N + c0) = make_float2(o0, o1);
                } else {
                    float q0 = aux0[r*128 + c0], q1v = aux0[r*128 + c0 + 1];
                    float t0 = aux2[r*256 + 128 + c0], t1 = aux2[r*256 + 128 + c0 + 1];
                    *reinterpret_cast<float2*>(C + (long)r*N + c0) =
                        make_float2(q0 + sigm(t0)*v0, q1v + sigm(t1)*v1);
                }
            }
        }
    }
}

// ---------------- LayerNorm + adaLN (warp per row) ----------------
__device__ __forceinline__ float warp_sum(float v)
{
    v += __shfl_xor_sync(0xffffffffu, v, 16);
    v += __shfl_xor_sync(0xffffffffu, v, 8);
    v += __shfl_xor_sync(0xffffffffu, v, 4);
    v += __shfl_xor_sync(0xffffffffu, v, 2);
    v += __shfl_xor_sync(0xffffffffu, v, 1);
    return v;
}

__global__ __launch_bounds__(128) void ln1_kernel(const float* __restrict__ q,
                           const float* __restrict__ ln_g, const float* __restrict__ ln_b)
{
    int row = blockIdx.x*4 + (threadIdx.x >> 5);
    int lane = threadIdx.x & 31;
    float4 x = *reinterpret_cast<const float4*>(q + row*DAD + lane*4);
    float mean = warp_sum(x.x + x.y + x.z + x.w) * (1.0f/128.0f);
    float dx = x.x-mean, dy = x.y-mean, dz = x.z-mean, dw = x.w-mean;
    float var = warp_sum(dx*dx + dy*dy + dz*dz + dw*dw) * (1.0f/128.0f);
    float rstd = rsqrtf(var + 1e-5f);
    float4 gg = *reinterpret_cast<const float4*>(ln_g + lane*4);
    float4 bb = *reinterpret_cast<const float4*>(ln_b + lane*4);
    float4 g1 = *reinterpret_cast<const float4*>(&g_ada[row*512 + lane*4]);
    float4 b1 = *reinterpret_cast<const float4*>(&g_ada[row*512 + 128 + lane*4]);
    float4 o;
    o.x = (1.0f+g1.x)*(dx*rstd*gg.x + bb.x) + b1.x;
    o.y = (1.0f+g1.y)*(dy*rstd*gg.y + bb.y) + b1.y;
    o.z = (1.0f+g1.z)*(dz*rstd*gg.z + bb.z) + b1.z;
    o.w = (1.0f+g1.w)*(dw*rstd*gg.w + bb.w) + b1.w;
    *reinterpret_cast<float4*>(&g_qn[row*DAD + lane*4]) = o;
}

__global__ __launch_bounds__(128) void ln2_kernel()
{
    int row = blockIdx.x*4 + (threadIdx.x >> 5);
    int lane = threadIdx.x & 31;
    float4 x = *reinterpret_cast<const float4*>(&g_q1[row*DAD + lane*4]);
    float mean = warp_sum(x.x + x.y + x.z + x.w) * (1.0f/128.0f);
    float dx = x.x-mean, dy = x.y-mean, dz = x.z-mean, dw = x.w-mean;
    float var = warp_sum(dx*dx + dy*dy + dz*dz + dw*dw) * (1.0f/128.0f);
    float rstd = rsqrtf(var + 1e-5f);
    float4 g2 = *reinterpret_cast<const float4*>(&g_ada[row*512 + 256 + lane*4]);
    float4 b2 = *reinterpret_cast<const float4*>(&g_ada[row*512 + 384 + lane*4]);
    float4 o;
    o.x = (1.0f+g2.x)*(dx*rstd) + b2.x;
    o.y = (1.0f+g2.y)*(dy*rstd) + b2.y;
    o.z = (1.0f+g2.z)*(dz*rstd) + b2.z;
    o.w = (1.0f+g2.w)*(dw*rstd) + b2.w;
    *reinterpret_cast<float4*>(&g_qn2[row*DAD + lane*4]) = o;
}

// ---------------- windowed attention: one warp per (atom, head) ----------------
__global__ __launch_bounds__(256) void attn_kernel()
{
    const int lane = threadIdx.x & 31;
    const int gw = blockIdx.x * 8 + (threadIdx.x >> 5);
    const int i = gw >> 2;
    const int h = gw & 3;
    const float scale = 0.17677669529663687f;  // 1/sqrt(32)

    float qv = g_qkvg[i*512 + h*DHEAD + lane];
    float s[WW];
    float mx = -1e30f;
    #pragma unroll
    for (int jj = 0; jj < WW; ++jj) {
        int j = i - WIN + jj;
        float sc = -1e30f;
        if (j >= 0 && j < NATOMS) {
            float kv = g_qkvg[j*512 + 128 + h*DHEAD + lane];
            float dp = warp_sum(qv * kv);
            sc = dp * scale + g_biasw[(i*WW + jj)*NHEAD + h];
        }
        s[jj] = sc;
        mx = fmaxf(mx, sc);
    }
    float sum = 0.0f;
    #pragma unroll
    for (int jj = 0; jj < WW; ++jj) {
        float e = __expf(s[jj] - mx);
        s[jj] = e;
        sum += e;
    }
    float inv = 1.0f / sum;
    float out = 0.0f;
    #pragma unroll
    for (int jj = 0; jj < WW; ++jj) {
        int j = i - WIN + jj;
        if (j >= 0 && j < NATOMS)
            out += s[jj] * inv * g_qkvg[j*512 + 256 + h*DHEAD + lane];
    }
    g_att[i*DAD + h*DHEAD + lane] = out;
}

// ---------------- launch ----------------
extern "C" void kernel_launch(void* const* d_in, const int* in_sizes, int n_in,
                              void* d_out, int out_size)
{
    const float* q        = (const float*)d_in[0];
    const float* c_atom   = (const float*)d_in[1];
    const float* h_cond   = (const float*)d_in[2];
    const float* p_lm     = (const float*)d_in[3];
    const float* t_emb    = (const float*)d_in[4];
    const float* cpw      = (const float*)d_in[5];
    const float* cpb      = (const float*)d_in[6];
    const float* a1w      = (const float*)d_in[7];
    const float* a1b      = (const float*)d_in[8];
    const float* a2w      = (const float*)d_in[9];
    const float* a2b      = (const float*)d_in[10];
    const float* ln_g     = (const float*)d_in[11];
    const float* ln_b     = (const float*)d_in[12];
    const float* wq       = (const float*)d_in[13];
    const float* wk       = (const float*)d_in[14];
    const float* wv       = (const float*)d_in[15];
    const float* wg       = (const float*)d_in[16];
    const float* wo       = (const float*)d_in[17];
    const float* pair_w   = (const float*)d_in[18];
    const float* pair_b   = (const float*)d_in[19];
    const float* g1w      = (const float*)d_in[20];
    const float* g1b      = (const float*)d_in[21];
    const float* g2w      = (const float*)d_in[22];
    const float* g2b      = (const float*)d_in[23];
    const float* sw1      = (const float*)d_in[24];
    const float* sw3      = (const float*)d_in[25];
    const float* sw2      = (const float*)d_in[26];
    const int*   p_lm_idx = (const int*)d_in[27];
    const int*   token_idx= (const int*)d_in[28];
    float* out = (float*)d_out;

    pack_kernel<<<128, 256>>>(wq, wk, wv, wg, a1w, a1b, a2w, a2b,
                              g1w, g1b, g2w, g2b, sw1, sw3, cpb, t_emb);
    scatter_init<<<528, 256>>>();
    scatter_pass1<<<NPAIR/256, 256>>>(p_lm_idx);
    scatter_pass2<<<NPAIR/256, 256>>>(p_lm_idx, p_lm, pair_w, pair_b);

    float* d_cond;  cudaGetSymbolAddress((void**)&d_cond,  g_cond);
    float* d_ada;   cudaGetSymbolAddress((void**)&d_ada,   g_ada);
    float* d_qn;    cudaGetSymbolAddress((void**)&d_qn,    g_qn);
    float* d_qkvg;  cudaGetSymbolAddress((void**)&d_qkvg,  g_qkvg);
    float* d_att;   cudaGetSymbolAddress((void**)&d_att,   g_att);
    float* d_q1;    cudaGetSymbolAddress((void**)&d_q1,    g_q1);
    float* d_qn2;   cudaGetSymbolAddress((void**)&d_qn2,   g_qn2);
    float* d_hh;    cudaGetSymbolAddress((void**)&d_hh,    g_hh);
    float* d_gate;  cudaGetSymbolAddress((void**)&d_gate,  g_gate);
    float* d_wqkvg; cudaGetSymbolAddress((void**)&d_wqkvg, g_wqkvg);
    float* d_wadaln;cudaGetSymbolAddress((void**)&d_wadaln,g_wadaln);
    float* d_badaln;cudaGetSymbolAddress((void**)&d_badaln,g_badaln);
    float* d_wgate; cudaGetSymbolAddress((void**)&d_wgate, g_wgate);
    float* d_bgate; cudaGetSymbolAddress((void**)&d_bgate, g_bgate);
    float* d_wsw13; cudaGetSymbolAddress((void**)&d_wsw13, g_wsw13);
    float* d_bias2; cudaGetSymbolAddress((void**)&d_bias2, g_bias2);

    // cond = t_emb + h_cond[token_idx] @ cond_proj_w + cond_proj_b   (M=4096,N=128,K=512)
    tgemm<64,64,32,2,2,0><<<dim3(2,64), 128>>>(h_cond, cpw, d_bias2, d_cond,
                                               NATOMS, 128, 512, token_idx, nullptr, nullptr, nullptr);
    // adaLN 1+2 fused: (N=512,K=128)
    tgemm<128,64,32,4,2,0><<<dim3(8,32), 256>>>(d_cond, d_wadaln, d_badaln, d_ada,
                                                NATOMS, 512, 128, nullptr, nullptr, nullptr, nullptr);
    // gates 1+2 fused from c_atom: (N=256,K=128)
    tgemm<128,64,32,4,2,0><<<dim3(4,32), 256>>>(c_atom, d_wgate, d_bgate, d_gate,
                                                NATOMS, 256, 128, nullptr, nullptr, nullptr, nullptr);
    // qn = adaLN-modulated LayerNorm(q)
    ln1_kernel<<<NATOMS/4, 128>>>(q, ln_g, ln_b);
    // QKVG fused: (N=512,K=128)
    tgemm<128,64,32,4,2,0><<<dim3(8,32), 256>>>(d_qn, d_wqkvg, nullptr, d_qkvg,
                                                NATOMS, 512, 128, nullptr, nullptr, nullptr, nullptr);
    // windowed attention
    attn_kernel<<<NATOMS*NHEAD/8, 256>>>();
    // q1 = (q + sigm(G)*(att@wo)) * (1+sigm(gate1))   (N=128,K=128, fused epilogue)
    tgemm<64,64,32,2,2,2><<<dim3(2,64), 128>>>(d_att, wo, nullptr, d_q1,
                                               NATOMS, 128, 128, nullptr, q, d_qkvg, d_gate);
    // second LN + adaLN2
    ln2_kernel<<<NATOMS/4, 128>>>();
    // swiglu up fused with silu*mul: (N=1024 interleaved -> out 512)
    tgemm<128,64,32,4,2,1><<<dim3(16,32), 256>>>(d_qn2, d_wsw13, nullptr, d_hh,
                                                 NATOMS, 1024, 128, nullptr, nullptr, nullptr, nullptr);
    // swiglu down fused with final residual: (N=128,K=512)
    tgemm<64,64,32,2,2,3><<<dim3(2,64), 128>>>(d_hh, sw2, nullptr, out,
                                               NATOMS, 128, 512, nullptr, d_q1, nullptr, d_gate);
}

// round 7
// speedup vs baseline: 1.5643x; 1.0016x over previous
#include <cuda_runtime.h>
#include <math.h>
#include <stdint.h>

// Problem constants (B=1)
#define NATOMS 4096
#define DAD    128
#define NPAIR  32768
#define NHEAD  4
#define DHEAD  32
#define DFF    512
#define WIN    16
#define WW     33   // window width

// ---------------- scratch (device globals; no allocation) ----------------
__device__ float g_cond [NATOMS*DAD];
__device__ float g_ada  [NATOMS*512];      // [g1|b1|g2|b2] per row
__device__ float g_qn   [NATOMS*DAD];
__device__ float g_qkvg [NATOMS*512];      // [Q|K|V|G] per row
__device__ float g_att  [NATOMS*DAD];
__device__ float g_q1   [NATOMS*DAD];
__device__ float g_qn2  [NATOMS*DAD];
__device__ float g_hh   [NATOMS*DFF];
__device__ float g_gate [NATOMS*256];      // [gate1|gate2]
__device__ float g_biasw[NATOMS*WW*NHEAD];
__device__ int   g_winner[NATOMS*WW];
// packed weights
__device__ float g_wqkvg [DAD*512];
__device__ float g_wadaln[DAD*512];
__device__ float g_badaln[512];
__device__ float g_wgate [DAD*256];
__device__ float g_bgate [256];
__device__ float g_wsw13 [DAD*1024];       // interleaved: col 2c = sw1_c, 2c+1 = sw3_c
__device__ float g_bias2 [DAD];

__device__ __forceinline__ float sigm(float x) { return 1.0f / (1.0f + __expf(-x)); }

__device__ __forceinline__ uint32_t f2tf32(float x)
{
    uint32_t r;
    asm("cvt.rna.tf32.f32 %0, %1;" : "=r"(r) : "f"(x));
    return r;
}

__device__ __forceinline__ void mma_tf32(float* c, const uint32_t* a, const uint32_t* b)
{
    asm volatile(
        "mma.sync.aligned.m16n8k8.row.col.f32.tf32.tf32.f32 "
        "{%0,%1,%2,%3}, {%4,%5,%6,%7}, {%8,%9}, {%0,%1,%2,%3};\n"
        : "+f"(c[0]), "+f"(c[1]), "+f"(c[2]), "+f"(c[3])
        : "r"(a[0]), "r"(a[1]), "r"(a[2]), "r"(a[3]), "r"(b[0]), "r"(b[1]));
}

// ---------------- weight packing ----------------
__global__ void pack_kernel(const float* __restrict__ wq, const float* __restrict__ wk,
                            const float* __restrict__ wv, const float* __restrict__ wg,
                            const float* __restrict__ a1w, const float* __restrict__ a1b,
                            const float* __restrict__ a2w, const float* __restrict__ a2b,
                            const float* __restrict__ g1w, const float* __restrict__ g1b,
                            const float* __restrict__ g2w, const float* __restrict__ g2b,
                            const float* __restrict__ sw1, const float* __restrict__ sw3,
                            const float* __restrict__ cpb, const float* __restrict__ temb)
{
    int i = blockIdx.x * blockDim.x + threadIdx.x;
    int stride = gridDim.x * blockDim.x;
    for (int e = i; e < 128*128; e += stride) {
        int k = e >> 7, n = e & 127;
        g_wqkvg[k*512 +       n] = wq[e];
        g_wqkvg[k*512 + 128 + n] = wk[e];
        g_wqkvg[k*512 + 256 + n] = wv[e];
        g_wqkvg[k*512 + 384 + n] = wg[e];
        g_wgate[k*256 +       n] = g1w[e];
        g_wgate[k*256 + 128 + n] = g2w[e];
    }
    for (int e = i; e < 128*256; e += stride) {
        int k = e >> 8, n = e & 255;
        g_wadaln[k*512 +       n] = a1w[e];
        g_wadaln[k*512 + 256 + n] = a2w[e];
    }
    for (int e = i; e < 128*512; e += stride) {
        int k = e >> 9, n = e & 511;
        g_wsw13[k*1024 + 2*n    ] = sw1[e];
        g_wsw13[k*1024 + 2*n + 1] = sw3[e];
    }
    for (int e = i; e < 256; e += stride) {
        g_badaln[e]       = a1b[e];
        g_badaln[256 + e] = a2b[e];
    }
    for (int e = i; e < 128; e += stride) {
        g_bgate[e]       = g1b[e];
        g_bgate[128 + e] = g2b[e];
        g_bias2[e]       = cpb[e] + temb[e];
    }
}

// ---------------- pair-bias scatter (deterministic last-wins) ----------------
__global__ void scatter_init()
{
    int i = blockIdx.x * blockDim.x + threadIdx.x;
    int stride = gridDim.x * blockDim.x;
    for (int e = i; e < NATOMS*WW; e += stride) g_winner[e] = -1;
    for (int e = i; e < NATOMS*WW*NHEAD; e += stride) g_biasw[e] = 0.0f;
}

__global__ void scatter_pass1(const int* __restrict__ idx)
{
    int p = blockIdx.x * blockDim.x + threadIdx.x;
    if (p >= NPAIR) return;
    int qi = idx[2*p], kj = idx[2*p+1];
    int d = kj - qi;
    if (d >= -WIN && d <= WIN && qi >= 0 && qi < NATOMS && kj >= 0 && kj < NATOMS)
        atomicMax(&g_winner[qi*WW + d + WIN], p);
}

__global__ void scatter_pass2(const int* __restrict__ idx,
                              const float* __restrict__ p_lm,
                              const float* __restrict__ pair_w,
                              const float* __restrict__ pair_b)
{
    int p = blockIdx.x * blockDim.x + threadIdx.x;
    if (p >= NPAIR) return;
    int qi = idx[2*p], kj = idx[2*p+1];
    int d = kj - qi;
    if (!(d >= -WIN && d <= WIN && qi >= 0 && qi < NATOMS && kj >= 0 && kj < NATOMS)) return;
    int slot = qi*WW + d + WIN;
    if (g_winner[slot] != p) return;
    #pragma unroll
    for (int h = 0; h < NHEAD; ++h) {
        float b = pair_b[h];
        #pragma unroll
        for (int k = 0; k < 16; ++k) b += p_lm[p*16 + k] * pair_w[k*NHEAD + h];
        g_biasw[slot*NHEAD + h] = b;
    }
}

// ---------------- pipelined TF32 tensor-core GEMM ----------------
// C[M,N] = A[M,K] @ B[K,N]; double-buffered smem, one sync per BK=32 k-iter.
// MODE 0: +bias plain store. 1: swiglu (interleaved h1/h3 -> silu(h1)*h3, out N/2).
// 2: q1 fuse: C = (aux0 + sigm(aux1_G)*acc) * (1+sigm(aux2_gate1)).
// 3: final fuse: C = aux0 + sigm(aux2_gate2)*acc.
template<int BM, int BN, int BK, int WM, int WN, int MODE>
__global__ __launch_bounds__(32*WM*WN)
void tgemm(const float* __restrict__ A, const float* __restrict__ Bm,
           const float* __restrict__ bias, float* __restrict__ C,
           int M, int N, int K, const int* __restrict__ rowidx,
           const float* __restrict__ aux0, const float* __restrict__ aux1,
           const float* __restrict__ aux2)
{
    constexpr int THREADS = 32*WM*WN;
    constexpr int WTM = BM/WM, WTN = BN/WN;
    constexpr int AM = WTM/16, AN = WTN/8;
    constexpr int AS = BK + 4;   // stride ≡ 4 (mod 32) -> conflict-free frag loads
    constexpr int BS = BN + 4;
    constexpr int LA = BM*BK/(4*THREADS);
    constexpr int LB = BK*BN/(4*THREADS);
    constexpr int A_TPR = BK/4;              // threads per A row (float4)
    constexpr int A_RSTEP = THREADS/A_TPR;
    constexpr int B_TPR = BN/4;
    constexpr int B_KSTEP = THREADS/B_TPR;

    __shared__ uint32_t As[2][BM*AS];
    __shared__ uint32_t Bs[2][BK*BS];

    const int tid = threadIdx.x;
    const int wid = tid >> 5, lane = tid & 31;
    const int gid = lane >> 2, tig = lane & 3;
    const int warpM = wid % WM, warpN = wid / WM;
    const int rowBase = blockIdx.y * BM, colBase = blockIdx.x * BN;

    const int a_r = tid / A_TPR;
    const int a_k = (tid % A_TPR) * 4;
    const int b_k = tid / B_TPR;
    const int b_n = (tid % B_TPR) * 4;

    long arowg[LA];
    #pragma unroll
    for (int a = 0; a < LA; ++a) {
        int r = rowBase + a_r + a*A_RSTEP;
        arowg[a] = rowidx ? (long)rowidx[r] : (long)r;
    }

    float4 ra[LA], rb[LB];

    auto loadg = [&](int it) {
        int k0 = it * BK;
        #pragma unroll
        for (int a = 0; a < LA; ++a)
            ra[a] = *reinterpret_cast<const float4*>(A + arowg[a]*K + k0 + a_k);
        #pragma unroll
        for (int b = 0; b < LB; ++b)
            rb[b] = *reinterpret_cast<const float4*>(Bm + (long)(k0 + b_k + b*B_KSTEP)*N + colBase + b_n);
    };
    auto stores = [&](int bf) {
        #pragma unroll
        for (int a = 0; a < LA; ++a) {
            uint32_t* p = &As[bf][(a_r + a*A_RSTEP)*AS + a_k];
            p[0]=f2tf32(ra[a].x); p[1]=f2tf32(ra[a].y); p[2]=f2tf32(ra[a].z); p[3]=f2tf32(ra[a].w);
        }
        #pragma unroll
        for (int b = 0; b < LB; ++b) {
            uint32_t* p = &Bs[bf][(b_k + b*B_KSTEP)*BS + b_n];
            p[0]=f2tf32(rb[b].x); p[1]=f2tf32(rb[b].y); p[2]=f2tf32(rb[b].z); p[3]=f2tf32(rb[b].w);
        }
    };

    float acc[AM][AN][4] = {};

    loadg(0); stores(0); __syncthreads();
    const int nIter = K / BK;
    int bf = 0;
    for (int it = 0; it < nIter; ++it) {
        if (it + 1 < nIter) loadg(it + 1);
        #pragma unroll
        for (int ks = 0; ks < BK/8; ++ks) {
            const int kk = ks * 8;
            uint32_t af[AM][4], bfr[AN][2];
            #pragma unroll
            for (int mi = 0; mi < AM; ++mi) {
                int r0 = warpM*WTM + mi*16 + gid;
                af[mi][0] = As[bf][r0*AS + kk + tig];
                af[mi][1] = As[bf][(r0+8)*AS + kk + tig];
                af[mi][2] = As[bf][r0*AS + kk + tig + 4];
                af[mi][3] = As[bf][(r0+8)*AS + kk + tig + 4];
            }
            #pragma unroll
            for (int ni = 0; ni < AN; ++ni) {
                int n0 = warpN*WTN + ni*8 + gid;
                bfr[ni][0] = Bs[bf][(kk + tig)*BS + n0];
                bfr[ni][1] = Bs[bf][(kk + tig + 4)*BS + n0];
            }
            #pragma unroll
            for (int mi = 0; mi < AM; ++mi)
                #pragma unroll
                for (int ni = 0; ni < AN; ++ni)
                    mma_tf32(acc[mi][ni], af[mi], bfr[ni]);
        }
        if (it + 1 < nIter) stores(bf ^ 1);
        __syncthreads();
        bf ^= 1;
    }

    // ---------------- epilogue ----------------
    #pragma unroll
    for (int mi = 0; mi < AM; ++mi) {
        #pragma unroll
        for (int ni = 0; ni < AN; ++ni) {
            int c0 = colBase + warpN*WTN + ni*8 + 2*tig;
            #pragma unroll
            for (int rh = 0; rh < 2; ++rh) {
                int r = rowBase + warpM*WTM + mi*16 + gid + rh*8;
                float v0 = acc[mi][ni][rh*2 + 0];
                float v1 = acc[mi][ni][rh*2 + 1];
                if (MODE == 0) {
                    if (bias) { v0 += bias[c0]; v1 += bias[c0+1]; }
                    *reinterpret_cast<float2*>(C + (long)r*N + c0) = make_float2(v0, v1);
                } else if (MODE == 1) {
                    // interleaved (h1, h3) -> silu(h1)*h3, out width N/2
                    C[(long)r*(N >> 1) + (c0 >> 1)] = v0 * sigm(v0) * v1;
                } else if (MODE == 2) {
                    float q0 = aux0[r*128 + c0],   q1v = aux0[r*128 + c0 + 1];
                    float G0 = aux1[r*512 + 384 + c0], G1 = aux1[r*512 + 384 + c0 + 1];
                    float t0 = aux2[r*256 + c0],   t1 = aux2[r*256 + c0 + 1];
                    float o0 = (q0 + sigm(G0)*v0) * (1.0f + sigm(t0));
                    float o1 = (q1v + sigm(G1)*v1) * (1.0f + sigm(t1));
                    *reinterpret_cast<float2*>(C + (long)r*N + c0) = make_float2(o0, o1);
                } else {
                    float q0 = aux0[r*128 + c0], q1v = aux0[r*128 + c0 + 1];
                    float t0 = aux2[r*256 + 128 + c0], t1 = aux2[r*256 + 128 + c0 + 1];
                    *reinterpret_cast<float2*>(C + (long)r*N + c0) =
                        make_float2(q0 + sigm(t0)*v0, q1v + sigm(t1)*v1);
                }
            }
        }
    }
}

// ---------------- LayerNorm + adaLN (warp per row) ----------------
__device__ __forceinline__ float warp_sum(float v)
{
    v += __shfl_xor_sync(0xffffffffu, v, 16);
    v += __shfl_xor_sync(0xffffffffu, v, 8);
    v += __shfl_xor_sync(0xffffffffu, v, 4);
    v += __shfl_xor_sync(0xffffffffu, v, 2);
    v += __shfl_xor_sync(0xffffffffu, v, 1);
    return v;
}

__global__ __launch_bounds__(128) void ln1_kernel(const float* __restrict__ q,
                           const float* __restrict__ ln_g, const float* __restrict__ ln_b)
{
    int row = blockIdx.x*4 + (threadIdx.x >> 5);
    int lane = threadIdx.x & 31;
    float4 x = *reinterpret_cast<const float4*>(q + row*DAD + lane*4);
    float mean = warp_sum(x.x + x.y + x.z + x.w) * (1.0f/128.0f);
    float dx = x.x-mean, dy = x.y-mean, dz = x.z-mean, dw = x.w-mean;
    float var = warp_sum(dx*dx + dy*dy + dz*dz + dw*dw) * (1.0f/128.0f);
    float rstd = rsqrtf(var + 1e-5f);
    float4 gg = *reinterpret_cast<const float4*>(ln_g + lane*4);
    float4 bb = *reinterpret_cast<const float4*>(ln_b + lane*4);
    float4 g1 = *reinterpret_cast<const float4*>(&g_ada[row*512 + lane*4]);
    float4 b1 = *reinterpret_cast<const float4*>(&g_ada[row*512 + 128 + lane*4]);
    float4 o;
    o.x = (1.0f+g1.x)*(dx*rstd*gg.x + bb.x) + b1.x;
    o.y = (1.0f+g1.y)*(dy*rstd*gg.y + bb.y) + b1.y;
    o.z = (1.0f+g1.z)*(dz*rstd*gg.z + bb.z) + b1.z;
    o.w = (1.0f+g1.w)*(dw*rstd*gg.w + bb.w) + b1.w;
    *reinterpret_cast<float4*>(&g_qn[row*DAD + lane*4]) = o;
}

__global__ __launch_bounds__(128) void ln2_kernel()
{
    int row = blockIdx.x*4 + (threadIdx.x >> 5);
    int lane = threadIdx.x & 31;
    float4 x = *reinterpret_cast<const float4*>(&g_q1[row*DAD + lane*4]);
    float mean = warp_sum(x.x + x.y + x.z + x.w) * (1.0f/128.0f);
    float dx = x.x-mean, dy = x.y-mean, dz = x.z-mean, dw = x.w-mean;
    float var = warp_sum(dx*dx + dy*dy + dz*dz + dw*dw) * (1.0f/128.0f);
    float rstd = rsqrtf(var + 1e-5f);
    float4 g2 = *reinterpret_cast<const float4*>(&g_ada[row*512 + 256 + lane*4]);
    float4 b2 = *reinterpret_cast<const float4*>(&g_ada[row*512 + 384 + lane*4]);
    float4 o;
    o.x = (1.0f+g2.x)*(dx*rstd) + b2.x;
    o.y = (1.0f+g2.y)*(dy*rstd) + b2.y;
    o.z = (1.0f+g2.z)*(dz*rstd) + b2.z;
    o.w = (1.0f+g2.w)*(dw*rstd) + b2.w;
    *reinterpret_cast<float4*>(&g_qn2[row*DAD + lane*4]) = o;
}

// ---------------- windowed attention: one warp per (atom, head) ----------------
__global__ __launch_bounds__(256) void attn_kernel()
{
    const int lane = threadIdx.x & 31;
    const int gw = blockIdx.x * 8 + (threadIdx.x >> 5);
    const int i = gw >> 2;
    const int h = gw & 3;
    const float scale = 0.17677669529663687f;  // 1/sqrt(32)

    float qv = g_qkvg[i*512 + h*DHEAD + lane];
    float s[WW];
    float mx = -1e30f;
    #pragma unroll
    for (int jj = 0; jj < WW; ++jj) {
        int j = i - WIN + jj;
        float sc = -1e30f;
        if (j >= 0 && j < NATOMS) {
            float kv = g_qkvg[j*512 + 128 + h*DHEAD + lane];
            float dp = warp_sum(qv * kv);
            sc = dp * scale + g_biasw[(i*WW + jj)*NHEAD + h];
        }
        s[jj] = sc;
        mx = fmaxf(mx, sc);
    }
    float sum = 0.0f;
    #pragma unroll
    for (int jj = 0; jj < WW; ++jj) {
        float e = __expf(s[jj] - mx);
        s[jj] = e;
        sum += e;
    }
    float inv = 1.0f / sum;
    float out = 0.0f;
    #pragma unroll
    for (int jj = 0; jj < WW; ++jj) {
        int j = i - WIN + jj;
        if (j >= 0 && j < NATOMS)
            out += s[jj] * inv * g_qkvg[j*512 + 256 + h*DHEAD + lane];
    }
    g_att[i*DAD + h*DHEAD + lane] = out;
}

// ---------------- launch ----------------
extern "C" void kernel_launch(void* const* d_in, const int* in_sizes, int n_in,
                              void* d_out, int out_size)
{
    const float* q        = (const float*)d_in[0];
    const float* c_atom   = (const float*)d_in[1];
    const float* h_cond   = (const float*)d_in[2];
    const float* p_lm     = (const float*)d_in[3];
    const float* t_emb    = (const float*)d_in[4];
    const float* cpw      = (const float*)d_in[5];
    const float* cpb      = (const float*)d_in[6];
    const float* a1w      = (const float*)d_in[7];
    const float* a1b      = (const float*)d_in[8];
    const float* a2w      = (const float*)d_in[9];
    const float* a2b      = (const float*)d_in[10];
    const float* ln_g     = (const float*)d_in[11];
    const float* ln_b     = (const float*)d_in[12];
    const float* wq       = (const float*)d_in[13];
    const float* wk       = (const float*)d_in[14];
    const float* wv       = (const float*)d_in[15];
    const float* wg       = (const float*)d_in[16];
    const float* wo       = (const float*)d_in[17];
    const float* pair_w   = (const float*)d_in[18];
    const float* pair_b   = (const float*)d_in[19];
    const float* g1w      = (const float*)d_in[20];
    const float* g1b      = (const float*)d_in[21];
    const float* g2w      = (const float*)d_in[22];
    const float* g2b      = (const float*)d_in[23];
    const float* sw1      = (const float*)d_in[24];
    const float* sw3      = (const float*)d_in[25];
    const float* sw2      = (const float*)d_in[26];
    const int*   p_lm_idx = (const int*)d_in[27];
    const int*   token_idx= (const int*)d_in[28];
    float* out = (float*)d_out;

    pack_kernel<<<128, 256>>>(wq, wk, wv, wg, a1w, a1b, a2w, a2b,
                              g1w, g1b, g2w, g2b, sw1, sw3, cpb, t_emb);
    scatter_init<<<528, 256>>>();
    scatter_pass1<<<NPAIR/256, 256>>>(p_lm_idx);
    scatter_pass2<<<NPAIR/256, 256>>>(p_lm_idx, p_lm, pair_w, pair_b);

    float* d_cond;  cudaGetSymbolAddress((void**)&d_cond,  g_cond);
    float* d_ada;   cudaGetSymbolAddress((void**)&d_ada,   g_ada);
    float* d_qn;    cudaGetSymbolAddress((void**)&d_qn,    g_qn);
    float* d_qkvg;  cudaGetSymbolAddress((void**)&d_qkvg,  g_qkvg);
    float* d_att;   cudaGetSymbolAddress((void**)&d_att,   g_att);
    float* d_q1;    cudaGetSymbolAddress((void**)&d_q1,    g_q1);
    float* d_qn2;   cudaGetSymbolAddress((void**)&d_qn2,   g_qn2);
    float* d_hh;    cudaGetSymbolAddress((void**)&d_hh,    g_hh);
    float* d_gate;  cudaGetSymbolAddress((void**)&d_gate,  g_gate);
    float* d_wqkvg; cudaGetSymbolAddress((void**)&d_wqkvg, g_wqkvg);
    float* d_wadaln;cudaGetSymbolAddress((void**)&d_wadaln,g_wadaln);
    float* d_badaln;cudaGetSymbolAddress((void**)&d_badaln,g_badaln);
    float* d_wgate; cudaGetSymbolAddress((void**)&d_wgate, g_wgate);
    float* d_bgate; cudaGetSymbolAddress((void**)&d_bgate, g_bgate);
    float* d_wsw13; cudaGetSymbolAddress((void**)&d_wsw13, g_wsw13);
    float* d_bias2; cudaGetSymbolAddress((void**)&d_bias2, g_bias2);

    // cond = t_emb + h_cond[token_idx] @ cond_proj_w + cond_proj_b   (M=4096,N=128,K=512)
    tgemm<64,64,32,2,2,0><<<dim3(2,64), 128>>>(h_cond, cpw, d_bias2, d_cond,
                                               NATOMS, 128, 512, token_idx, nullptr, nullptr, nullptr);
    // adaLN 1+2 fused: (N=512,K=128)
    tgemm<128,64,32,4,2,0><<<dim3(8,32), 256>>>(d_cond, d_wadaln, d_badaln, d_ada,
                                                NATOMS, 512, 128, nullptr, nullptr, nullptr, nullptr);
    // gates 1+2 fused from c_atom: (N=256,K=128)
    tgemm<128,64,32,4,2,0><<<dim3(4,32), 256>>>(c_atom, d_wgate, d_bgate, d_gate,
                                                NATOMS, 256, 128, nullptr, nullptr, nullptr, nullptr);
    // qn = adaLN-modulated LayerNorm(q)
    ln1_kernel<<<NATOMS/4, 128>>>(q, ln_g, ln_b);
    // QKVG fused: (N=512,K=128)
    tgemm<128,64,32,4,2,0><<<dim3(8,32), 256>>>(d_qn, d_wqkvg, nullptr, d_qkvg,
                                                NATOMS, 512, 128, nullptr, nullptr, nullptr, nullptr);
    // windowed attention
    attn_kernel<<<NATOMS*NHEAD/8, 256>>>();
    // q1 = (q + sigm(G)*(att@wo)) * (1+sigm(gate1))   (N=128,K=128, fused epilogue)
    tgemm<64,64,32,2,2,2><<<dim3(2,64), 128>>>(d_att, wo, nullptr, d_q1,
                                               NATOMS, 128, 128, nullptr, q, d_qkvg, d_gate);
    // second LN + adaLN2
    ln2_kernel<<<NATOMS/4, 128>>>();
    // swiglu up fused with silu*mul: (N=1024 interleaved -> out 512)
    tgemm<128,64,32,4,2,1><<<dim3(16,32), 256>>>(d_qn2, d_wsw13, nullptr, d_hh,
                                                 NATOMS, 1024, 128, nullptr, nullptr, nullptr, nullptr);
    // swiglu down fused with final residual: (N=128,K=512)
    tgemm<64,64,32,2,2,3><<<dim3(2,64), 128>>>(d_hh, sw2, nullptr, out,
                                               NATOMS, 128, 512, nullptr, d_q1, nullptr, d_gate);
}